// round 5
// baseline (speedup 1.0000x reference)
#include <cuda_runtime.h>
#include <cuda_fp16.h>
#include <math_constants.h>

#define N_NODES 50000
#define N_EDGES 800000
#define IN_CH   64
#define HEADS   4
#define OUT_CH  64
#define HC      (HEADS * OUT_CH)   // 256
#define NEG_SLOPE 0.2f
#define NBLK_NODES 196             // ceil(50000/256)

typedef unsigned long long ull;

// ---------------- device scratch ----------------
__device__ __align__(16) __half2 g_xth[(size_t)N_NODES * (HC / 2)]; // [N,128] fp16x2
__device__ __align__(16) float g_asrc[N_NODES * HEADS];
__device__ __align__(16) float g_adst[N_NODES * HEADS];
__device__ __align__(16) float4 g_w[N_EDGES];      // per-edge softmax numerators
__device__ __align__(16) ull  g_W2[32 * HC];       // W2[kk*256+c] = (W[2kk][c], W[2kk+1][c])
__device__ int   g_count[N_NODES];
__device__ int   g_offs[N_NODES];
__device__ int   g_cursor[N_NODES];
__device__ int   g_esrc[N_EDGES];
__device__ int   g_bsum[256];
__device__ int   g_boff[256];

__device__ __forceinline__ float leaky(float v) {
    return (v > 0.0f) ? v : NEG_SLOPE * v;
}

__device__ __forceinline__ void fma2(ull& d, ull a, ull b) {
    asm("fma.rn.f32x2 %0, %1, %2, %0;" : "+l"(d) : "l"(a), "l"(b));
}
__device__ __forceinline__ float2 unpack2(ull v) {
    float2 r;
    asm("mov.b64 {%0, %1}, %2;" : "=f"(r.x), "=f"(r.y) : "l"(v));
    return r;
}
__device__ __forceinline__ ull pack2(float lo, float hi) {
    ull r;
    asm("mov.b64 %0, {%1, %2};" : "=l"(r) : "f"(lo), "f"(hi));
    return r;
}

// ---------------- K0: prep — zero counts + k-pair repack of W ----------------
__global__ void prep_kernel(const float* __restrict__ W) {
    int i = blockIdx.x * blockDim.x + threadIdx.x;
    if (i < 32 * HC) {
        int kk = i >> 8, c = i & 255;
        g_W2[i] = pack2(W[(size_t)(2 * kk) * HC + c], W[(size_t)(2 * kk + 1) * HC + c]);
    }
    if (i < N_NODES) g_count[i] = 0;
}

// ---------------- K1: xt = x @ W via FFMA2, fused fp16 pack + attention logits ----
// 256 threads; 16 nodes x 256 outs; thread (ty,tx) -> nodes n0..n0+3, outs o0..o0+3.
__global__ void gemm_kernel(const float* __restrict__ x,
                            const float* __restrict__ att_src,
                            const float* __restrict__ att_dst) {
    __shared__ float xs[16][64];
    const int tid  = threadIdx.x;
    const int nblk = blockIdx.x * 16;

    for (int i = tid; i < 16 * 64; i += 256) {
        int n = i >> 6, k = i & 63;
        int node = nblk + n;
        xs[n][k] = (node < N_NODES) ? x[(size_t)node * IN_CH + k] : 0.0f;
    }
    __syncthreads();

    const int tx = tid & 63;
    const int ty = tid >> 6;
    const int o0 = tx * 4;
    const int n0 = ty * 4;
    const int h  = o0 >> 6;

    ull acc[4][4];   // [node][chan], each = two k-partial sums
#pragma unroll
    for (int a = 0; a < 4; a++)
#pragma unroll
        for (int b = 0; b < 4; b++) acc[a][b] = 0ull;

#pragma unroll 8
    for (int kk = 0; kk < 32; kk++) {
        ulonglong2 wa = __ldg((const ulonglong2*)(g_W2 + kk * HC + o0));
        ulonglong2 wb = __ldg((const ulonglong2*)(g_W2 + kk * HC + o0 + 2));
#pragma unroll
        for (int nn = 0; nn < 4; nn++) {
            ull xp = *(const ull*)&xs[n0 + nn][2 * kk];   // broadcast LDS.64
            fma2(acc[nn][0], xp, wa.x);
            fma2(acc[nn][1], xp, wa.y);
            fma2(acc[nn][2], xp, wb.x);
            fma2(acc[nn][3], xp, wb.y);
        }
    }

    float a_[4][4];
#pragma unroll
    for (int nn = 0; nn < 4; nn++)
#pragma unroll
        for (int c = 0; c < 4; c++) {
            float2 p = unpack2(acc[nn][c]);
            a_[nn][c] = p.x + p.y;
        }

    // fp16-pack store
#pragma unroll
    for (int nn = 0; nn < 4; nn++) {
        int node = nblk + n0 + nn;
        if (node < N_NODES) {
            __half2 p0 = __floats2half2_rn(a_[nn][0], a_[nn][1]);
            __half2 p1 = __floats2half2_rn(a_[nn][2], a_[nn][3]);
            uint2 v = make_uint2(*(unsigned*)&p0, *(unsigned*)&p1);
            *(uint2*)(g_xth + (size_t)node * (HC / 2) + (o0 >> 1)) = v;
        }
    }

    // fused attention logits: reduce over 16 lanes covering one head
    float a0 = __ldg(att_src + o0),     a1 = __ldg(att_src + o0 + 1);
    float a2 = __ldg(att_src + o0 + 2), a3 = __ldg(att_src + o0 + 3);
    float d0 = __ldg(att_dst + o0),     d1 = __ldg(att_dst + o0 + 1);
    float d2 = __ldg(att_dst + o0 + 2), d3 = __ldg(att_dst + o0 + 3);

    float ps[4], pd[4];
#pragma unroll
    for (int nn = 0; nn < 4; nn++) {
        ps[nn] = a_[nn][0] * a0 + a_[nn][1] * a1 + a_[nn][2] * a2 + a_[nn][3] * a3;
        pd[nn] = a_[nn][0] * d0 + a_[nn][1] * d1 + a_[nn][2] * d2 + a_[nn][3] * d3;
    }
#pragma unroll
    for (int off = 8; off > 0; off >>= 1) {
#pragma unroll
        for (int nn = 0; nn < 4; nn++) {
            ps[nn] += __shfl_down_sync(0xFFFFFFFFu, ps[nn], off, 16);
            pd[nn] += __shfl_down_sync(0xFFFFFFFFu, pd[nn], off, 16);
        }
    }
    if ((tx & 15) == 0) {
#pragma unroll
        for (int nn = 0; nn < 4; nn++) {
            int node = nblk + n0 + nn;
            if (node < N_NODES) {
                g_asrc[node * 4 + h] = ps[nn];
                g_adst[node * 4 + h] = pd[nn];
            }
        }
    }
}

// ---------------- K2: CSR build ----------------
__global__ void count_kernel(const int* __restrict__ ei) {
    int i = blockIdx.x * blockDim.x + threadIdx.x;
    if (i < N_EDGES / 4) {
        int4 d = __ldg((const int4*)(ei + N_EDGES) + i);
        atomicAdd(&g_count[d.x], 1);
        atomicAdd(&g_count[d.y], 1);
        atomicAdd(&g_count[d.z], 1);
        atomicAdd(&g_count[d.w], 1);
    }
}

__global__ void scanA_kernel() {
    __shared__ int wsum[8];
    int i = blockIdx.x * 256 + threadIdx.x;
    int c = (i < N_NODES) ? g_count[i] : 0;
    int v = c;
#pragma unroll
    for (int off = 16; off > 0; off >>= 1)
        v += __shfl_down_sync(0xFFFFFFFFu, v, off);
    if ((threadIdx.x & 31) == 0) wsum[threadIdx.x >> 5] = v;
    __syncthreads();
    if (threadIdx.x == 0) {
        int s = 0;
#pragma unroll
        for (int w = 0; w < 8; w++) s += wsum[w];
        g_bsum[blockIdx.x] = s;
    }
}

__global__ void scanB_kernel() {
    __shared__ int sm[256];
    int t = threadIdx.x;
    int v = (t < NBLK_NODES) ? g_bsum[t] : 0;
    sm[t] = v;
    __syncthreads();
    for (int off = 1; off < 256; off <<= 1) {
        int u = (t >= off) ? sm[t - off] : 0;
        __syncthreads();
        sm[t] += u;
        __syncthreads();
    }
    if (t < NBLK_NODES) g_boff[t] = sm[t] - v;
}

__global__ void scanC_kernel() {
    __shared__ int sm[256];
    int t = threadIdx.x;
    int i = blockIdx.x * 256 + t;
    int c = (i < N_NODES) ? g_count[i] : 0;
    sm[t] = c;
    __syncthreads();
    for (int off = 1; off < 256; off <<= 1) {
        int u = (t >= off) ? sm[t - off] : 0;
        __syncthreads();
        sm[t] += u;
        __syncthreads();
    }
    if (i < N_NODES) {
        int off = g_boff[blockIdx.x] + sm[t] - c;
        g_offs[i] = off;
        g_cursor[i] = off;
    }
}

// ---------------- K3: scatter + edge-weight precompute ----------------
__global__ void scatter_kernel(const int* __restrict__ ei) {
    int i = blockIdx.x * blockDim.x + threadIdx.x;
    if (i >= N_EDGES) return;
    int src = __ldg(ei + i);
    int dst = __ldg(ei + N_EDGES + i);
    int pos = atomicAdd(&g_cursor[dst], 1);
    g_esrc[pos] = src;
    float4 as = *(const float4*)(g_asrc + src * 4);
    float4 ad = *(const float4*)(g_adst + dst * 4);
    float4 w;
    w.x = __expf(leaky(as.x + ad.x));
    w.y = __expf(leaky(as.y + ad.y));
    w.z = __expf(leaky(as.z + ad.z));
    w.w = __expf(leaky(as.w + ad.w));
    g_w[pos] = w;
}

// ---------------- K4: gather-aggregate + head-mean + relu + fc ----------------
// one warp per dst node. lane owns bytes [16*lane,16*lane+16) of the 512B row:
// 8 channels of head (lane>>3), channel-in-head base cb=(lane&7)*8.
__global__ void agg_kernel(const float* __restrict__ bias,
                           const float* __restrict__ fc_w,
                           const float* __restrict__ fc_b,
                           float* __restrict__ out) {
    int i    = (blockIdx.x * blockDim.x + threadIdx.x) >> 5;
    int lane = threadIdx.x & 31;
    if (i >= N_NODES) return;

    const int h  = lane >> 3;
    const int cb = (lane & 7) * 8;
    const int start = g_offs[i];
    const int deg   = g_count[i];

    const float selfw = __expf(leaky(g_asrc[i * 4 + h] + g_adst[i * 4 + h]));
    const float* wflat = (const float*)g_w;

    float acc[8] = {0, 0, 0, 0, 0, 0, 0, 0};
    float s = 0.0f;

    // software pipeline: prefetch next (j, w)
    int jn; float wn;
    if (deg > 0) { jn = __ldg(g_esrc + start); wn = __ldg(wflat + 4 * start + h); }
    else         { jn = i; wn = selfw; }

    for (int e = 0; e <= deg; e++) {
        int j = jn; float w = wn;
        int en = e + 1;
        if (en < deg)       { jn = __ldg(g_esrc + start + en); wn = __ldg(wflat + 4 * (start + en) + h); }
        else if (en == deg) { jn = i; wn = selfw; }

        s += w;
        uint4 v = __ldg((const uint4*)(g_xth + (size_t)j * (HC / 2)) + lane);
        float2 f0 = __half22float2(*(__half2*)&v.x);
        float2 f1 = __half22float2(*(__half2*)&v.y);
        float2 f2 = __half22float2(*(__half2*)&v.z);
        float2 f3 = __half22float2(*(__half2*)&v.w);
        acc[0] += w * f0.x; acc[1] += w * f0.y;
        acc[2] += w * f1.x; acc[3] += w * f1.y;
        acc[4] += w * f2.x; acc[5] += w * f2.y;
        acc[6] += w * f3.x; acc[7] += w * f3.y;
    }

    // normalize by this head's softmax sum, then mean over heads via xor-shuffles
    float inv = 0.25f / s;
#pragma unroll
    for (int c = 0; c < 8; c++) acc[c] *= inv;
#pragma unroll
    for (int c = 0; c < 8; c++) {
        acc[c] += __shfl_xor_sync(0xFFFFFFFFu, acc[c], 8);
        acc[c] += __shfl_xor_sync(0xFFFFFFFFu, acc[c], 16);
    }

    float4 b0 = __ldg((const float4*)(bias + cb));
    float4 b1 = __ldg((const float4*)(bias + cb + 4));
    float4 f0 = __ldg((const float4*)(fc_w + cb));
    float4 f1 = __ldg((const float4*)(fc_w + cb + 4));

    float p = fmaxf(acc[0] + b0.x, 0.0f) * f0.x
            + fmaxf(acc[1] + b0.y, 0.0f) * f0.y
            + fmaxf(acc[2] + b0.z, 0.0f) * f0.z
            + fmaxf(acc[3] + b0.w, 0.0f) * f0.w
            + fmaxf(acc[4] + b1.x, 0.0f) * f1.x
            + fmaxf(acc[5] + b1.y, 0.0f) * f1.y
            + fmaxf(acc[6] + b1.z, 0.0f) * f1.z
            + fmaxf(acc[7] + b1.w, 0.0f) * f1.w;

    p += __shfl_down_sync(0xFFFFFFFFu, p, 4, 8);
    p += __shfl_down_sync(0xFFFFFFFFu, p, 2, 8);
    p += __shfl_down_sync(0xFFFFFFFFu, p, 1, 8);

    if (lane == 0) out[i] = p + __ldg(fc_b);
}

// ---------------- launch ----------------
extern "C" void kernel_launch(void* const* d_in, const int* in_sizes, int n_in,
                              void* d_out, int out_size) {
    const float* x        = (const float*)d_in[0];
    const int*   ei       = (const int*)d_in[1];     // int32 [2, E]
    const float* W        = (const float*)d_in[2];
    const float* att_src  = (const float*)d_in[3];
    const float* att_dst  = (const float*)d_in[4];
    const float* bias     = (const float*)d_in[5];
    const float* fc_w     = (const float*)d_in[6];
    const float* fc_b     = (const float*)d_in[7];
    float*       out      = (float*)d_out;

    (void)in_sizes; (void)n_in; (void)out_size;

    prep_kernel<<<NBLK_NODES, 256>>>(W);
    gemm_kernel<<<(N_NODES + 15) / 16, 256>>>(x, att_src, att_dst);
    count_kernel<<<(N_EDGES / 4 + 255) / 256, 256>>>(ei);
    scanA_kernel<<<NBLK_NODES, 256>>>();
    scanB_kernel<<<1, 256>>>();
    scanC_kernel<<<NBLK_NODES, 256>>>();
    scatter_kernel<<<(N_EDGES + 255) / 256, 256>>>(ei);
    agg_kernel<<<(N_NODES * 32 + 255) / 256, 256>>>(bias, fc_w, fc_b, out);
}

// round 6
// speedup vs baseline: 1.2153x; 1.2153x over previous
#include <cuda_runtime.h>
#include <cuda_fp16.h>
#include <math_constants.h>

#define N_NODES 50000
#define N_EDGES 800000
#define IN_CH   64
#define HEADS   4
#define OUT_CH  64
#define HC      (HEADS * OUT_CH)   // 256
#define NEG_SLOPE 0.2f
#define NBLK_NODES 196             // ceil(50000/256)

// ---------------- device scratch ----------------
__device__ __align__(16) __half2 g_xth[(size_t)N_NODES * (HC / 2)]; // [N,128] fp16x2
__device__ __align__(16) float g_asrc[N_NODES * HEADS];
__device__ __align__(16) float g_adst[N_NODES * HEADS];
__device__ __align__(16) float4 g_w[N_EDGES];      // per-edge softmax numerators
__device__ int   g_count[N_NODES];
__device__ int   g_offs[N_NODES];
__device__ int   g_cursor[N_NODES];
__device__ int   g_esrc[N_EDGES];
__device__ int   g_bsum[256];
__device__ int   g_boff[256];

__device__ __forceinline__ float leaky(float v) {
    return (v > 0.0f) ? v : NEG_SLOPE * v;
}

// ---------------- K1: xt = x @ W (scalar FFMA 4x4), fused fp16 pack + logits ----
__global__ void gemm_kernel(const float* __restrict__ x,
                            const float* __restrict__ W,
                            const float* __restrict__ att_src,
                            const float* __restrict__ att_dst) {
    __shared__ float xs[16][64];
    const int tid  = threadIdx.x;
    const int nblk = blockIdx.x * 16;

    for (int i = tid; i < 16 * 64; i += 256) {
        int n = i >> 6, k = i & 63;
        int node = nblk + n;
        xs[n][k] = (node < N_NODES) ? x[(size_t)node * IN_CH + k] : 0.0f;
    }
    __syncthreads();

    const int tx = tid & 63;
    const int ty = tid >> 6;
    const int o0 = tx * 4;
    const int n0 = ty * 4;
    const int h  = o0 >> 6;

    float acc[4][4];
#pragma unroll
    for (int a = 0; a < 4; a++)
#pragma unroll
        for (int b = 0; b < 4; b++) acc[a][b] = 0.0f;

#pragma unroll 8
    for (int k = 0; k < 64; k++) {
        float4 w4 = __ldg((const float4*)(W + (size_t)k * HC + o0));
        float xv0 = xs[n0 + 0][k];
        float xv1 = xs[n0 + 1][k];
        float xv2 = xs[n0 + 2][k];
        float xv3 = xs[n0 + 3][k];
        acc[0][0] += xv0 * w4.x; acc[0][1] += xv0 * w4.y; acc[0][2] += xv0 * w4.z; acc[0][3] += xv0 * w4.w;
        acc[1][0] += xv1 * w4.x; acc[1][1] += xv1 * w4.y; acc[1][2] += xv1 * w4.z; acc[1][3] += xv1 * w4.w;
        acc[2][0] += xv2 * w4.x; acc[2][1] += xv2 * w4.y; acc[2][2] += xv2 * w4.z; acc[2][3] += xv2 * w4.w;
        acc[3][0] += xv3 * w4.x; acc[3][1] += xv3 * w4.y; acc[3][2] += xv3 * w4.z; acc[3][3] += xv3 * w4.w;
    }

    // fp16-pack store
#pragma unroll
    for (int nn = 0; nn < 4; nn++) {
        int node = nblk + n0 + nn;
        if (node < N_NODES) {
            __half2 p0 = __floats2half2_rn(acc[nn][0], acc[nn][1]);
            __half2 p1 = __floats2half2_rn(acc[nn][2], acc[nn][3]);
            uint2 v = make_uint2(*(unsigned*)&p0, *(unsigned*)&p1);
            *(uint2*)(g_xth + (size_t)node * (HC / 2) + (o0 >> 1)) = v;
        }
    }

    // fused attention logits: reduce over 16 lanes covering one head
    float a0 = __ldg(att_src + o0),     a1 = __ldg(att_src + o0 + 1);
    float a2 = __ldg(att_src + o0 + 2), a3 = __ldg(att_src + o0 + 3);
    float d0 = __ldg(att_dst + o0),     d1 = __ldg(att_dst + o0 + 1);
    float d2 = __ldg(att_dst + o0 + 2), d3 = __ldg(att_dst + o0 + 3);

    float ps[4], pd[4];
#pragma unroll
    for (int nn = 0; nn < 4; nn++) {
        ps[nn] = acc[nn][0] * a0 + acc[nn][1] * a1 + acc[nn][2] * a2 + acc[nn][3] * a3;
        pd[nn] = acc[nn][0] * d0 + acc[nn][1] * d1 + acc[nn][2] * d2 + acc[nn][3] * d3;
    }
#pragma unroll
    for (int off = 8; off > 0; off >>= 1) {
#pragma unroll
        for (int nn = 0; nn < 4; nn++) {
            ps[nn] += __shfl_down_sync(0xFFFFFFFFu, ps[nn], off, 16);
            pd[nn] += __shfl_down_sync(0xFFFFFFFFu, pd[nn], off, 16);
        }
    }
    if ((tx & 15) == 0) {
#pragma unroll
        for (int nn = 0; nn < 4; nn++) {
            int node = nblk + n0 + nn;
            if (node < N_NODES) {
                g_asrc[node * 4 + h] = ps[nn];
                g_adst[node * 4 + h] = pd[nn];
            }
        }
    }
}

// ---------------- CSR build ----------------
__global__ void zero_count_kernel() {
    int i = blockIdx.x * blockDim.x + threadIdx.x;
    if (i < N_NODES) g_count[i] = 0;
}

__global__ void count_kernel(const int* __restrict__ ei) {
    int i = blockIdx.x * blockDim.x + threadIdx.x;
    if (i < N_EDGES / 4) {
        int4 d = __ldg((const int4*)(ei + N_EDGES) + i);
        atomicAdd(&g_count[d.x], 1);
        atomicAdd(&g_count[d.y], 1);
        atomicAdd(&g_count[d.z], 1);
        atomicAdd(&g_count[d.w], 1);
    }
}

__global__ void scanA_kernel() {
    __shared__ int wsum[8];
    int i = blockIdx.x * 256 + threadIdx.x;
    int c = (i < N_NODES) ? g_count[i] : 0;
    int v = c;
#pragma unroll
    for (int off = 16; off > 0; off >>= 1)
        v += __shfl_down_sync(0xFFFFFFFFu, v, off);
    if ((threadIdx.x & 31) == 0) wsum[threadIdx.x >> 5] = v;
    __syncthreads();
    if (threadIdx.x == 0) {
        int s = 0;
#pragma unroll
        for (int w = 0; w < 8; w++) s += wsum[w];
        g_bsum[blockIdx.x] = s;
    }
}

__global__ void scanB_kernel() {
    __shared__ int sm[256];
    int t = threadIdx.x;
    int v = (t < NBLK_NODES) ? g_bsum[t] : 0;
    sm[t] = v;
    __syncthreads();
    for (int off = 1; off < 256; off <<= 1) {
        int u = (t >= off) ? sm[t - off] : 0;
        __syncthreads();
        sm[t] += u;
        __syncthreads();
    }
    if (t < NBLK_NODES) g_boff[t] = sm[t] - v;
}

__global__ void scanC_kernel() {
    __shared__ int sm[256];
    int t = threadIdx.x;
    int i = blockIdx.x * 256 + t;
    int c = (i < N_NODES) ? g_count[i] : 0;
    sm[t] = c;
    __syncthreads();
    for (int off = 1; off < 256; off <<= 1) {
        int u = (t >= off) ? sm[t - off] : 0;
        __syncthreads();
        sm[t] += u;
        __syncthreads();
    }
    if (i < N_NODES) {
        int off = g_boff[blockIdx.x] + sm[t] - c;
        g_offs[i] = off;
        g_cursor[i] = off;
    }
}

// ---------------- scatter + edge-weight precompute ----------------
__global__ void scatter_kernel(const int* __restrict__ ei) {
    int i = blockIdx.x * blockDim.x + threadIdx.x;
    if (i >= N_EDGES) return;
    int src = __ldg(ei + i);
    int dst = __ldg(ei + N_EDGES + i);
    int pos = atomicAdd(&g_cursor[dst], 1);
    g_esrc[pos] = src;
    float4 as = *(const float4*)(g_asrc + src * 4);
    float4 ad = *(const float4*)(g_adst + dst * 4);
    float4 w;
    w.x = __expf(leaky(as.x + ad.x));
    w.y = __expf(leaky(as.y + ad.y));
    w.z = __expf(leaky(as.z + ad.z));
    w.w = __expf(leaky(as.w + ad.w));
    g_w[pos] = w;
}

// ---------------- agg: gather + head-mean + relu + fc (LDG.128 layout) --------
// one warp per dst node. lane owns bytes [16*lane,16*lane+16) of the 512B row:
// 8 channels of head (lane>>3), channel-in-head base cb=(lane&7)*8.
__global__ void agg_kernel(const float* __restrict__ bias,
                           const float* __restrict__ fc_w,
                           const float* __restrict__ fc_b,
                           float* __restrict__ out) {
    int i    = (blockIdx.x * blockDim.x + threadIdx.x) >> 5;
    int lane = threadIdx.x & 31;
    if (i >= N_NODES) return;

    const int h  = lane >> 3;
    const int cb = (lane & 7) * 8;
    const int start = g_offs[i];
    const int deg   = g_count[i];

    const float selfw = __expf(leaky(g_asrc[i * 4 + h] + g_adst[i * 4 + h]));
    const float* wflat = (const float*)g_w;

    float acc[8] = {0, 0, 0, 0, 0, 0, 0, 0};
    float s = 0.0f;

    int jn; float wn;
    if (deg > 0) { jn = __ldg(g_esrc + start); wn = __ldg(wflat + 4 * start + h); }
    else         { jn = i; wn = selfw; }

    for (int e = 0; e <= deg; e++) {
        int j = jn; float w = wn;
        int en = e + 1;
        if (en < deg)       { jn = __ldg(g_esrc + start + en); wn = __ldg(wflat + 4 * (start + en) + h); }
        else if (en == deg) { jn = i; wn = selfw; }

        s += w;
        uint4 v = __ldg((const uint4*)(g_xth + (size_t)j * (HC / 2)) + lane);
        float2 f0 = __half22float2(*(__half2*)&v.x);
        float2 f1 = __half22float2(*(__half2*)&v.y);
        float2 f2 = __half22float2(*(__half2*)&v.z);
        float2 f3 = __half22float2(*(__half2*)&v.w);
        acc[0] += w * f0.x; acc[1] += w * f0.y;
        acc[2] += w * f1.x; acc[3] += w * f1.y;
        acc[4] += w * f2.x; acc[5] += w * f2.y;
        acc[6] += w * f3.x; acc[7] += w * f3.y;
    }

    float inv = 0.25f / s;
#pragma unroll
    for (int c = 0; c < 8; c++) acc[c] *= inv;
#pragma unroll
    for (int c = 0; c < 8; c++) {
        acc[c] += __shfl_xor_sync(0xFFFFFFFFu, acc[c], 8);
        acc[c] += __shfl_xor_sync(0xFFFFFFFFu, acc[c], 16);
    }

    float4 b0 = __ldg((const float4*)(bias + cb));
    float4 b1 = __ldg((const float4*)(bias + cb + 4));
    float4 f0 = __ldg((const float4*)(fc_w + cb));
    float4 f1 = __ldg((const float4*)(fc_w + cb + 4));

    float p = fmaxf(acc[0] + b0.x, 0.0f) * f0.x
            + fmaxf(acc[1] + b0.y, 0.0f) * f0.y
            + fmaxf(acc[2] + b0.z, 0.0f) * f0.z
            + fmaxf(acc[3] + b0.w, 0.0f) * f0.w
            + fmaxf(acc[4] + b1.x, 0.0f) * f1.x
            + fmaxf(acc[5] + b1.y, 0.0f) * f1.y
            + fmaxf(acc[6] + b1.z, 0.0f) * f1.z
            + fmaxf(acc[7] + b1.w, 0.0f) * f1.w;

    p += __shfl_down_sync(0xFFFFFFFFu, p, 4, 8);
    p += __shfl_down_sync(0xFFFFFFFFu, p, 2, 8);
    p += __shfl_down_sync(0xFFFFFFFFu, p, 1, 8);

    if (lane == 0) out[i] = p + __ldg(fc_b);
}

// ---------------- launch ----------------
// NOTE: launch order puts gemm_kernel at index 3 — the ncu capture slot —
// so the next profile shows the GEMM. (CSR front-end is independent of gemm.)
extern "C" void kernel_launch(void* const* d_in, const int* in_sizes, int n_in,
                              void* d_out, int out_size) {
    const float* x        = (const float*)d_in[0];
    const int*   ei       = (const int*)d_in[1];     // int32 [2, E]
    const float* W        = (const float*)d_in[2];
    const float* att_src  = (const float*)d_in[3];
    const float* att_dst  = (const float*)d_in[4];
    const float* bias     = (const float*)d_in[5];
    const float* fc_w     = (const float*)d_in[6];
    const float* fc_b     = (const float*)d_in[7];
    float*       out      = (float*)d_out;

    (void)in_sizes; (void)n_in; (void)out_size;

    zero_count_kernel<<<NBLK_NODES, 256>>>();
    count_kernel<<<(N_EDGES / 4 + 255) / 256, 256>>>(ei);
    scanA_kernel<<<NBLK_NODES, 256>>>();
    gemm_kernel<<<(N_NODES + 15) / 16, 256>>>(x, W, att_src, att_dst);   // capture slot
    scanB_kernel<<<1, 256>>>();
    scanC_kernel<<<NBLK_NODES, 256>>>();
    scatter_kernel<<<(N_EDGES + 255) / 256, 256>>>(ei);
    agg_kernel<<<(N_NODES * 32 + 255) / 256, 256>>>(bias, fc_w, fc_b, out);
}

// round 7
// speedup vs baseline: 1.2256x; 1.0084x over previous
#include <cuda_runtime.h>
#include <cuda_fp16.h>
#include <mma.h>
#include <math_constants.h>

using namespace nvcuda;

#define N_NODES 50000
#define N_EDGES 800000
#define IN_CH   64
#define HEADS   4
#define OUT_CH  64
#define HC      (HEADS * OUT_CH)   // 256
#define NEG_SLOPE 0.2f
#define NBLK_NODES 196             // ceil(50000/256)
#define GEMM_TILE_N 32
#define NBLK_GEMM ((N_NODES + GEMM_TILE_N - 1) / GEMM_TILE_N)  // 1563

// ---------------- device scratch ----------------
__device__ __align__(16) __half2 g_xth[(size_t)N_NODES * (HC / 2)]; // [N,128] fp16x2
__device__ __align__(16) float g_asrc[N_NODES * HEADS];
__device__ __align__(16) float g_adst[N_NODES * HEADS];
__device__ __align__(16) float4 g_w[N_EDGES];      // per-edge softmax numerators
__device__ int   g_count[N_NODES];
__device__ int   g_offs[N_NODES];
__device__ int   g_cursor[N_NODES];
__device__ int   g_esrc[N_EDGES];
__device__ int   g_bsum[256];
__device__ int   g_boff[256];

__device__ __forceinline__ float leaky(float v) {
    return (v > 0.0f) ? v : NEG_SLOPE * v;
}

// ---------------- K1: xt = x @ W on tensor cores (tf32 wmma), fused epilogue ----
// block: 256 threads (8 warps), 32 nodes x 256 cols.
// warp w: col tiles [32w, 32w+32), node tiles rows 0-15 and 16-31.
__global__ void gemm_kernel(const float* __restrict__ x,
                            const float* __restrict__ W,
                            const float* __restrict__ att_src,
                            const float* __restrict__ att_dst) {
    __shared__ float xa[GEMM_TILE_N][72];        // x tile, padded
    __shared__ float st[GEMM_TILE_N][HC];        // fp32 result staging

    const int tid  = threadIdx.x;
    const int warp = tid >> 5;
    const int lane = tid & 31;
    const int nblk = blockIdx.x * GEMM_TILE_N;

    // load x tile [32 x 64] (zero-pad OOB nodes)
    for (int i = tid; i < GEMM_TILE_N * IN_CH; i += 256) {
        int n = i >> 6, k = i & 63;
        int node = nblk + n;
        xa[n][k] = (node < N_NODES) ? x[(size_t)node * IN_CH + k] : 0.0f;
    }
    __syncthreads();

    wmma::fragment<wmma::accumulator, 16, 16, 8, float> acc[2][2];
#pragma unroll
    for (int a = 0; a < 2; a++)
#pragma unroll
        for (int b = 0; b < 2; b++) wmma::fill_fragment(acc[a][b], 0.0f);

    const int c0 = warp * 32;
#pragma unroll
    for (int k0 = 0; k0 < IN_CH; k0 += 8) {
        wmma::fragment<wmma::matrix_a, 16, 16, 8, wmma::precision::tf32, wmma::row_major> a0, a1;
        wmma::fragment<wmma::matrix_b, 16, 16, 8, wmma::precision::tf32, wmma::row_major> b0, b1;
        wmma::load_matrix_sync(a0, &xa[0][k0], 72);
        wmma::load_matrix_sync(a1, &xa[16][k0], 72);
        wmma::load_matrix_sync(b0, W + (size_t)k0 * HC + c0, HC);
        wmma::load_matrix_sync(b1, W + (size_t)k0 * HC + c0 + 16, HC);
#pragma unroll
        for (int t = 0; t < a0.num_elements; t++) {
            a0.x[t] = wmma::__float_to_tf32(a0.x[t]);
            a1.x[t] = wmma::__float_to_tf32(a1.x[t]);
        }
#pragma unroll
        for (int t = 0; t < b0.num_elements; t++) {
            b0.x[t] = wmma::__float_to_tf32(b0.x[t]);
            b1.x[t] = wmma::__float_to_tf32(b1.x[t]);
        }
        wmma::mma_sync(acc[0][0], a0, b0, acc[0][0]);
        wmma::mma_sync(acc[0][1], a0, b1, acc[0][1]);
        wmma::mma_sync(acc[1][0], a1, b0, acc[1][0]);
        wmma::mma_sync(acc[1][1], a1, b1, acc[1][1]);
    }

    wmma::store_matrix_sync(&st[0][c0],       acc[0][0], HC, wmma::mem_row_major);
    wmma::store_matrix_sync(&st[0][c0 + 16],  acc[0][1], HC, wmma::mem_row_major);
    wmma::store_matrix_sync(&st[16][c0],      acc[1][0], HC, wmma::mem_row_major);
    wmma::store_matrix_sync(&st[16][c0 + 16], acc[1][1], HC, wmma::mem_row_major);
    __syncthreads();

    // ---- epilogue pass 1: attention logits (8 threads per node, stride-8 cols) ----
    {
        const int n   = tid >> 3;          // 0..31
        const int sub = tid & 7;
        const int node = nblk + n;
        float ps[4] = {0, 0, 0, 0};
        float pd[4] = {0, 0, 0, 0};
#pragma unroll
        for (int i = 0; i < 32; i++) {
            int col = sub + 8 * i;          // head = i>>3
            float v = st[n][col];
            ps[i >> 3] += v * __ldg(att_src + col);
            pd[i >> 3] += v * __ldg(att_dst + col);
        }
#pragma unroll
        for (int off = 4; off > 0; off >>= 1) {
#pragma unroll
            for (int h = 0; h < 4; h++) {
                ps[h] += __shfl_down_sync(0xFFFFFFFFu, ps[h], off);
                pd[h] += __shfl_down_sync(0xFFFFFFFFu, pd[h], off);
            }
        }
        if (sub == 0 && node < N_NODES) {
            *(float4*)(g_asrc + node * 4) = make_float4(ps[0], ps[1], ps[2], ps[3]);
            *(float4*)(g_adst + node * 4) = make_float4(pd[0], pd[1], pd[2], pd[3]);
        }
    }

    // ---- epilogue pass 2: fp16 pack, warp-per-row uint4 stores ----
#pragma unroll
    for (int rep = 0; rep < 4; rep++) {
        int n = warp + 8 * rep;
        int node = nblk + n;
        if (node < N_NODES) {
            float4 u = *(const float4*)&st[n][8 * lane];
            float4 v = *(const float4*)&st[n][8 * lane + 4];
            __half2 h0 = __floats2half2_rn(u.x, u.y);
            __half2 h1 = __floats2half2_rn(u.z, u.w);
            __half2 h2 = __floats2half2_rn(v.x, v.y);
            __half2 h3 = __floats2half2_rn(v.z, v.w);
            uint4 o = make_uint4(*(unsigned*)&h0, *(unsigned*)&h1,
                                 *(unsigned*)&h2, *(unsigned*)&h3);
            *(uint4*)(g_xth + (size_t)node * (HC / 2) + lane * 4) = o;
        }
    }
}

// ---------------- CSR build ----------------
__global__ void zero_count_kernel() {
    int i = blockIdx.x * blockDim.x + threadIdx.x;
    if (i < N_NODES) g_count[i] = 0;
}

__global__ void count_kernel(const int* __restrict__ ei) {
    int i = blockIdx.x * blockDim.x + threadIdx.x;
    if (i < N_EDGES / 4) {
        int4 d = __ldg((const int4*)(ei + N_EDGES) + i);
        atomicAdd(&g_count[d.x], 1);
        atomicAdd(&g_count[d.y], 1);
        atomicAdd(&g_count[d.z], 1);
        atomicAdd(&g_count[d.w], 1);
    }
}

__global__ void scanA_kernel() {
    __shared__ int wsum[8];
    int i = blockIdx.x * 256 + threadIdx.x;
    int c = (i < N_NODES) ? g_count[i] : 0;
    int v = c;
#pragma unroll
    for (int off = 16; off > 0; off >>= 1)
        v += __shfl_down_sync(0xFFFFFFFFu, v, off);
    if ((threadIdx.x & 31) == 0) wsum[threadIdx.x >> 5] = v;
    __syncthreads();
    if (threadIdx.x == 0) {
        int s = 0;
#pragma unroll
        for (int w = 0; w < 8; w++) s += wsum[w];
        g_bsum[blockIdx.x] = s;
    }
}

__global__ void scanB_kernel() {
    __shared__ int sm[256];
    int t = threadIdx.x;
    int v = (t < NBLK_NODES) ? g_bsum[t] : 0;
    sm[t] = v;
    __syncthreads();
    for (int off = 1; off < 256; off <<= 1) {
        int u = (t >= off) ? sm[t - off] : 0;
        __syncthreads();
        sm[t] += u;
        __syncthreads();
    }
    if (t < NBLK_NODES) g_boff[t] = sm[t] - v;
}

__global__ void scanC_kernel() {
    __shared__ int sm[256];
    int t = threadIdx.x;
    int i = blockIdx.x * 256 + t;
    int c = (i < N_NODES) ? g_count[i] : 0;
    sm[t] = c;
    __syncthreads();
    for (int off = 1; off < 256; off <<= 1) {
        int u = (t >= off) ? sm[t - off] : 0;
        __syncthreads();
        sm[t] += u;
        __syncthreads();
    }
    if (i < N_NODES) {
        int off = g_boff[blockIdx.x] + sm[t] - c;
        g_offs[i] = off;
        g_cursor[i] = off;
    }
}

// ---------------- scatter + edge-weight precompute ----------------
__global__ void scatter_kernel(const int* __restrict__ ei) {
    int i = blockIdx.x * blockDim.x + threadIdx.x;
    if (i >= N_EDGES) return;
    int src = __ldg(ei + i);
    int dst = __ldg(ei + N_EDGES + i);
    int pos = atomicAdd(&g_cursor[dst], 1);
    g_esrc[pos] = src;
    float4 as = *(const float4*)(g_asrc + src * 4);
    float4 ad = *(const float4*)(g_adst + dst * 4);
    float4 w;
    w.x = __expf(leaky(as.x + ad.x));
    w.y = __expf(leaky(as.y + ad.y));
    w.z = __expf(leaky(as.z + ad.z));
    w.w = __expf(leaky(as.w + ad.w));
    g_w[pos] = w;
}

// ---------------- agg: gather + head-mean + relu + fc (LDG.128 layout) --------
__global__ void agg_kernel(const float* __restrict__ bias,
                           const float* __restrict__ fc_w,
                           const float* __restrict__ fc_b,
                           float* __restrict__ out) {
    int i    = (blockIdx.x * blockDim.x + threadIdx.x) >> 5;
    int lane = threadIdx.x & 31;
    if (i >= N_NODES) return;

    const int h  = lane >> 3;
    const int cb = (lane & 7) * 8;
    const int start = g_offs[i];
    const int deg   = g_count[i];

    const float selfw = __expf(leaky(g_asrc[i * 4 + h] + g_adst[i * 4 + h]));
    const float* wflat = (const float*)g_w;

    float acc[8] = {0, 0, 0, 0, 0, 0, 0, 0};
    float s = 0.0f;

    int jn; float wn;
    if (deg > 0) { jn = __ldg(g_esrc + start); wn = __ldg(wflat + 4 * start + h); }
    else         { jn = i; wn = selfw; }

    for (int e = 0; e <= deg; e++) {
        int j = jn; float w = wn;
        int en = e + 1;
        if (en < deg)       { jn = __ldg(g_esrc + start + en); wn = __ldg(wflat + 4 * (start + en) + h); }
        else if (en == deg) { jn = i; wn = selfw; }

        s += w;
        uint4 v = __ldg((const uint4*)(g_xth + (size_t)j * (HC / 2)) + lane);
        float2 f0 = __half22float2(*(__half2*)&v.x);
        float2 f1 = __half22float2(*(__half2*)&v.y);
        float2 f2 = __half22float2(*(__half2*)&v.z);
        float2 f3 = __half22float2(*(__half2*)&v.w);
        acc[0] += w * f0.x; acc[1] += w * f0.y;
        acc[2] += w * f1.x; acc[3] += w * f1.y;
        acc[4] += w * f2.x; acc[5] += w * f2.y;
        acc[6] += w * f3.x; acc[7] += w * f3.y;
    }

    float inv = 0.25f / s;
#pragma unroll
    for (int c = 0; c < 8; c++) acc[c] *= inv;
#pragma unroll
    for (int c = 0; c < 8; c++) {
        acc[c] += __shfl_xor_sync(0xFFFFFFFFu, acc[c], 8);
        acc[c] += __shfl_xor_sync(0xFFFFFFFFu, acc[c], 16);
    }

    float4 b0 = __ldg((const float4*)(bias + cb));
    float4 b1 = __ldg((const float4*)(bias + cb + 4));
    float4 f0 = __ldg((const float4*)(fc_w + cb));
    float4 f1 = __ldg((const float4*)(fc_w + cb + 4));

    float p = fmaxf(acc[0] + b0.x, 0.0f) * f0.x
            + fmaxf(acc[1] + b0.y, 0.0f) * f0.y
            + fmaxf(acc[2] + b0.z, 0.0f) * f0.z
            + fmaxf(acc[3] + b0.w, 0.0f) * f0.w
            + fmaxf(acc[4] + b1.x, 0.0f) * f1.x
            + fmaxf(acc[5] + b1.y, 0.0f) * f1.y
            + fmaxf(acc[6] + b1.z, 0.0f) * f1.z
            + fmaxf(acc[7] + b1.w, 0.0f) * f1.w;

    p += __shfl_down_sync(0xFFFFFFFFu, p, 4, 8);
    p += __shfl_down_sync(0xFFFFFFFFu, p, 2, 8);
    p += __shfl_down_sync(0xFFFFFFFFu, p, 1, 8);

    if (lane == 0) out[i] = p + __ldg(fc_b);
}

// ---------------- launch ----------------
// gemm_kernel stays at launch index 3 (the ncu capture slot) to verify the
// tensor-core conversion (expect tensor>0%, dur ~15-18us).
extern "C" void kernel_launch(void* const* d_in, const int* in_sizes, int n_in,
                              void* d_out, int out_size) {
    const float* x        = (const float*)d_in[0];
    const int*   ei       = (const int*)d_in[1];     // int32 [2, E]
    const float* W        = (const float*)d_in[2];
    const float* att_src  = (const float*)d_in[3];
    const float* att_dst  = (const float*)d_in[4];
    const float* bias     = (const float*)d_in[5];
    const float* fc_w     = (const float*)d_in[6];
    const float* fc_b     = (const float*)d_in[7];
    float*       out      = (float*)d_out;

    (void)in_sizes; (void)n_in; (void)out_size;

    zero_count_kernel<<<NBLK_NODES, 256>>>();
    count_kernel<<<(N_EDGES / 4 + 255) / 256, 256>>>(ei);
    scanA_kernel<<<NBLK_NODES, 256>>>();
    gemm_kernel<<<NBLK_GEMM, 256>>>(x, W, att_src, att_dst);   // capture slot
    scanB_kernel<<<1, 256>>>();
    scanC_kernel<<<NBLK_NODES, 256>>>();
    scatter_kernel<<<(N_EDGES + 255) / 256, 256>>>(ei);
    agg_kernel<<<(N_NODES * 32 + 255) / 256, 256>>>(bias, fc_w, fc_b, out);
}

// round 8
// speedup vs baseline: 1.2856x; 1.0490x over previous
#include <cuda_runtime.h>
#include <cuda_fp16.h>
#include <mma.h>
#include <math_constants.h>

using namespace nvcuda;

#define N_NODES 50000
#define N_EDGES 800000
#define IN_CH   64
#define HEADS   4
#define OUT_CH  64
#define HC      (HEADS * OUT_CH)   // 256
#define NEG_SLOPE 0.2f
#define NBLK_NODES 196             // ceil(50000/256)

#define GT_M    32                 // nodes per gemm block
#define W_COLS  272                // 256 xt cols + 8 logit cols + 8 pad
#define W_LD    280                // smem leading dim (halves)
#define XA_LD   72                 // x tile leading dim (halves)
#define NBLK_GEMM ((N_NODES + GT_M - 1) / GT_M)   // 1563

// ---------------- device scratch ----------------
__device__ __align__(16) __half2 g_xth[(size_t)N_NODES * (HC / 2)]; // [N,128] fp16x2
__device__ __align__(16) __half  g_Wh[64 * W_COLS];                 // W'' fp16
__device__ __align__(16) float g_asrc[N_NODES * HEADS];
__device__ __align__(16) float g_adst[N_NODES * HEADS];
__device__ __align__(16) float4 g_w[N_EDGES];      // per-edge softmax numerators
__device__ int   g_count[N_NODES];
__device__ int   g_offs[N_NODES];
__device__ int   g_cursor[N_NODES];
__device__ int   g_esrc[N_EDGES];
__device__ int   g_bsum[256];
__device__ int   g_boff[256];

__device__ __forceinline__ float leaky(float v) {
    return (v > 0.0f) ? v : NEG_SLOPE * v;
}

// ---------------- K0: prep — zero counts + build fp16 W'' = [W | W@Vsrc | W@Vdst | 0]
__global__ void prep_kernel(const float* __restrict__ W,
                            const float* __restrict__ att_src,
                            const float* __restrict__ att_dst) {
    int i = blockIdx.x * blockDim.x + threadIdx.x;
    if (i < N_NODES) g_count[i] = 0;
    if (i < 64 * W_COLS) {
        int k = i / W_COLS, c = i % W_COLS;
        float v;
        if (c < HC) {
            v = W[(size_t)k * HC + c];
        } else if (c < HC + 8) {
            int h = (c - HC) & 3;
            const float* av = (c < HC + 4) ? att_src : att_dst;
            float s = 0.0f;
            for (int t = 0; t < OUT_CH; t++)
                s += W[(size_t)k * HC + h * OUT_CH + t] * av[h * OUT_CH + t];
            v = s;
        } else {
            v = 0.0f;
        }
        g_Wh[i] = __float2half(v);
    }
}

// ---------------- K1: xt = x @ W'' on fp16 HMMA; writes g_xth + g_asrc/g_adst ---
// 128 threads (4 warps): warp (mw, cw) = (warp>>1, warp&1).
// mw: 16-node tile; cw: col-tile range [0,9) or [9,17). Tile 16 = logit cols.
__global__ void __launch_bounds__(128) gemm_kernel(const float* __restrict__ x) {
    __shared__ __align__(16) __half xa[GT_M * XA_LD];
    __shared__ __align__(16) __half Ws[64 * W_LD];
    __shared__ __align__(16) float  stage[4][16 * 20];

    const int tid  = threadIdx.x;
    const int warp = tid >> 5;
    const int lane = tid & 31;
    const int nblk = blockIdx.x * GT_M;

    // x tile [32 x 64] fp32 -> fp16 (zero-pad OOB)
    for (int i = tid; i < GT_M * IN_CH; i += 128) {
        int n = i >> 6, k = i & 63;
        int node = nblk + n;
        xa[n * XA_LD + k] = __float2half((node < N_NODES) ? x[(size_t)node * IN_CH + k] : 0.0f);
    }
    // W'' [64 x 272] vectorized load into smem
    for (int i = tid; i < 64 * (W_COLS / 8); i += 128) {
        int k = i / (W_COLS / 8), c8 = i % (W_COLS / 8);
        *(uint4*)(Ws + k * W_LD + c8 * 8) = __ldg((const uint4*)(g_Wh + k * W_COLS) + c8);
    }
    __syncthreads();

    const int mw = warp >> 1;
    const int cw = warp & 1;
    const int ct_begin = cw ? 9 : 0;
    const int ct_end   = cw ? 17 : 9;

    wmma::fragment<wmma::matrix_a, 16, 16, 16, __half, wmma::row_major> af[4];
#pragma unroll
    for (int kk = 0; kk < 4; kk++)
        wmma::load_matrix_sync(af[kk], xa + (mw * 16) * XA_LD + kk * 16, XA_LD);

    float* st = stage[warp];
    __half* xth = (__half*)g_xth;

    for (int ct = ct_begin; ct < ct_end; ct++) {
        wmma::fragment<wmma::accumulator, 16, 16, 16, float> acc;
        wmma::fill_fragment(acc, 0.0f);
#pragma unroll
        for (int kk = 0; kk < 4; kk++) {
            wmma::fragment<wmma::matrix_b, 16, 16, 16, __half, wmma::row_major> bf;
            wmma::load_matrix_sync(bf, Ws + (kk * 16) * W_LD + ct * 16, W_LD);
            wmma::mma_sync(acc, af[kk], bf, acc);
        }
        wmma::store_matrix_sync(st, acc, 20, wmma::mem_row_major);
        __syncwarp();
        if (ct < 16) {
            // pack 16x16 fp32 -> fp16, one STG.128 per lane
            int row = lane & 15, ch = lane >> 4;
            int node = nblk + mw * 16 + row;
            if (node < N_NODES) {
                float4 u = *(const float4*)(st + row * 20 + ch * 8);
                float4 v = *(const float4*)(st + row * 20 + ch * 8 + 4);
                __half2 h0 = __floats2half2_rn(u.x, u.y);
                __half2 h1 = __floats2half2_rn(u.z, u.w);
                __half2 h2 = __floats2half2_rn(v.x, v.y);
                __half2 h3 = __floats2half2_rn(v.z, v.w);
                uint4 o = make_uint4(*(unsigned*)&h0, *(unsigned*)&h1,
                                     *(unsigned*)&h2, *(unsigned*)&h3);
                *(uint4*)(xth + (size_t)node * HC + ct * 16 + ch * 8) = o;
            }
        } else {
            // logit tile: cols 0..3 = asrc heads, 4..7 = adst heads
            if (lane < 16) {
                int node = nblk + mw * 16 + lane;
                if (node < N_NODES) {
                    *(float4*)(g_asrc + node * 4) = *(const float4*)(st + lane * 20);
                    *(float4*)(g_adst + node * 4) = *(const float4*)(st + lane * 20 + 4);
                }
            }
        }
        __syncwarp();
    }
}

// ---------------- CSR build ----------------
__global__ void count_kernel(const int* __restrict__ ei) {
    int i = blockIdx.x * blockDim.x + threadIdx.x;
    if (i < N_EDGES / 4) {
        int4 d = __ldg((const int4*)(ei + N_EDGES) + i);
        atomicAdd(&g_count[d.x], 1);
        atomicAdd(&g_count[d.y], 1);
        atomicAdd(&g_count[d.z], 1);
        atomicAdd(&g_count[d.w], 1);
    }
}

__global__ void scanA_kernel() {
    __shared__ int wsum[8];
    int i = blockIdx.x * 256 + threadIdx.x;
    int c = (i < N_NODES) ? g_count[i] : 0;
    int v = c;
#pragma unroll
    for (int off = 16; off > 0; off >>= 1)
        v += __shfl_down_sync(0xFFFFFFFFu, v, off);
    if ((threadIdx.x & 31) == 0) wsum[threadIdx.x >> 5] = v;
    __syncthreads();
    if (threadIdx.x == 0) {
        int s = 0;
#pragma unroll
        for (int w = 0; w < 8; w++) s += wsum[w];
        g_bsum[blockIdx.x] = s;
    }
}

__global__ void scanB_kernel() {
    __shared__ int sm[256];
    int t = threadIdx.x;
    int v = (t < NBLK_NODES) ? g_bsum[t] : 0;
    sm[t] = v;
    __syncthreads();
    for (int off = 1; off < 256; off <<= 1) {
        int u = (t >= off) ? sm[t - off] : 0;
        __syncthreads();
        sm[t] += u;
        __syncthreads();
    }
    if (t < NBLK_NODES) g_boff[t] = sm[t] - v;
}

__global__ void scanC_kernel() {
    __shared__ int sm[256];
    int t = threadIdx.x;
    int i = blockIdx.x * 256 + t;
    int c = (i < N_NODES) ? g_count[i] : 0;
    sm[t] = c;
    __syncthreads();
    for (int off = 1; off < 256; off <<= 1) {
        int u = (t >= off) ? sm[t - off] : 0;
        __syncthreads();
        sm[t] += u;
        __syncthreads();
    }
    if (i < N_NODES) {
        int off = g_boff[blockIdx.x] + sm[t] - c;
        g_offs[i] = off;
        g_cursor[i] = off;
    }
}

// ---------------- scatter + edge-weight precompute ----------------
__global__ void scatter_kernel(const int* __restrict__ ei) {
    int i = blockIdx.x * blockDim.x + threadIdx.x;
    if (i >= N_EDGES) return;
    int src = __ldg(ei + i);
    int dst = __ldg(ei + N_EDGES + i);
    int pos = atomicAdd(&g_cursor[dst], 1);
    g_esrc[pos] = src;
    float4 as = *(const float4*)(g_asrc + src * 4);
    float4 ad = *(const float4*)(g_adst + dst * 4);
    float4 w;
    w.x = __expf(leaky(as.x + ad.x));
    w.y = __expf(leaky(as.y + ad.y));
    w.z = __expf(leaky(as.z + ad.z));
    w.w = __expf(leaky(as.w + ad.w));
    g_w[pos] = w;
}

// ---------------- agg: gather + head-mean + relu + fc (LDG.128 layout) --------
__global__ void agg_kernel(const float* __restrict__ bias,
                           const float* __restrict__ fc_w,
                           const float* __restrict__ fc_b,
                           float* __restrict__ out) {
    int i    = (blockIdx.x * blockDim.x + threadIdx.x) >> 5;
    int lane = threadIdx.x & 31;
    if (i >= N_NODES) return;

    const int h  = lane >> 3;
    const int cb = (lane & 7) * 8;
    const int start = g_offs[i];
    const int deg   = g_count[i];

    const float selfw = __expf(leaky(g_asrc[i * 4 + h] + g_adst[i * 4 + h]));
    const float* wflat = (const float*)g_w;

    float acc[8] = {0, 0, 0, 0, 0, 0, 0, 0};
    float s = 0.0f;

    int jn; float wn;
    if (deg > 0) { jn = __ldg(g_esrc + start); wn = __ldg(wflat + 4 * start + h); }
    else         { jn = i; wn = selfw; }

    for (int e = 0; e <= deg; e++) {
        int j = jn; float w = wn;
        int en = e + 1;
        if (en < deg)       { jn = __ldg(g_esrc + start + en); wn = __ldg(wflat + 4 * (start + en) + h); }
        else if (en == deg) { jn = i; wn = selfw; }

        s += w;
        uint4 v = __ldg((const uint4*)(g_xth + (size_t)j * (HC / 2)) + lane);
        float2 f0 = __half22float2(*(__half2*)&v.x);
        float2 f1 = __half22float2(*(__half2*)&v.y);
        float2 f2 = __half22float2(*(__half2*)&v.z);
        float2 f3 = __half22float2(*(__half2*)&v.w);
        acc[0] += w * f0.x; acc[1] += w * f0.y;
        acc[2] += w * f1.x; acc[3] += w * f1.y;
        acc[4] += w * f2.x; acc[5] += w * f2.y;
        acc[6] += w * f3.x; acc[7] += w * f3.y;
    }

    float inv = 0.25f / s;
#pragma unroll
    for (int c = 0; c < 8; c++) acc[c] *= inv;
#pragma unroll
    for (int c = 0; c < 8; c++) {
        acc[c] += __shfl_xor_sync(0xFFFFFFFFu, acc[c], 8);
        acc[c] += __shfl_xor_sync(0xFFFFFFFFu, acc[c], 16);
    }

    float4 b0 = __ldg((const float4*)(bias + cb));
    float4 b1 = __ldg((const float4*)(bias + cb + 4));
    float4 f0 = __ldg((const float4*)(fc_w + cb));
    float4 f1 = __ldg((const float4*)(fc_w + cb + 4));

    float p = fmaxf(acc[0] + b0.x, 0.0f) * f0.x
            + fmaxf(acc[1] + b0.y, 0.0f) * f0.y
            + fmaxf(acc[2] + b0.z, 0.0f) * f0.z
            + fmaxf(acc[3] + b0.w, 0.0f) * f0.w
            + fmaxf(acc[4] + b1.x, 0.0f) * f1.x
            + fmaxf(acc[5] + b1.y, 0.0f) * f1.y
            + fmaxf(acc[6] + b1.z, 0.0f) * f1.z
            + fmaxf(acc[7] + b1.w, 0.0f) * f1.w;

    p += __shfl_down_sync(0xFFFFFFFFu, p, 4, 8);
    p += __shfl_down_sync(0xFFFFFFFFu, p, 2, 8);
    p += __shfl_down_sync(0xFFFFFFFFu, p, 1, 8);

    if (lane == 0) out[i] = p + __ldg(fc_b);
}

// ---------------- launch ----------------
// gemm_kernel at launch index 3 (ncu capture slot) to verify the HMMA redesign.
extern "C" void kernel_launch(void* const* d_in, const int* in_sizes, int n_in,
                              void* d_out, int out_size) {
    const float* x        = (const float*)d_in[0];
    const int*   ei       = (const int*)d_in[1];     // int32 [2, E]
    const float* W        = (const float*)d_in[2];
    const float* att_src  = (const float*)d_in[3];
    const float* att_dst  = (const float*)d_in[4];
    const float* bias     = (const float*)d_in[5];
    const float* fc_w     = (const float*)d_in[6];
    const float* fc_b     = (const float*)d_in[7];
    float*       out      = (float*)d_out;

    (void)in_sizes; (void)n_in; (void)out_size;

    prep_kernel<<<NBLK_NODES, 256>>>(W, att_src, att_dst);
    count_kernel<<<(N_EDGES / 4 + 255) / 256, 256>>>(ei);
    scanA_kernel<<<NBLK_NODES, 256>>>();
    gemm_kernel<<<NBLK_GEMM, 128>>>(x);                        // capture slot
    scanB_kernel<<<1, 256>>>();
    scanC_kernel<<<NBLK_NODES, 256>>>();
    scatter_kernel<<<(N_EDGES + 255) / 256, 256>>>(ei);
    agg_kernel<<<(N_NODES * 32 + 255) / 256, 256>>>(bias, fc_w, fc_b, out);
}

// round 9
// speedup vs baseline: 1.3109x; 1.0197x over previous
#include <cuda_runtime.h>
#include <cuda_fp16.h>
#include <mma.h>
#include <math_constants.h>

using namespace nvcuda;

#define N_NODES 50000
#define N_EDGES 800000
#define IN_CH   64
#define HEADS   4
#define OUT_CH  64
#define HC      (HEADS * OUT_CH)   // 256
#define NEG_SLOPE 0.2f
#define NBLK_NODES 196             // ceil(50000/256)

#define GT_M    64                 // nodes per gemm block
#define W_COLS  272                // 256 xt cols + 8 logit cols + 8 pad
#define W_LD    280                // smem leading dim (halves)
#define XA_LD   72                 // x tile leading dim (halves)
#define NBLK_GEMM ((N_NODES + GT_M - 1) / GT_M)   // 782

// ---------------- device scratch ----------------
__device__ __align__(16) __half2 g_xth[(size_t)N_NODES * (HC / 2)]; // [N,128] fp16x2
__device__ __align__(16) __half  g_Wh[64 * W_COLS];                 // W'' fp16
__device__ __align__(16) float g_asrc[N_NODES * HEADS];
__device__ __align__(16) float g_adst[N_NODES * HEADS];
__device__ __align__(16) float4 g_w[N_EDGES];      // per-edge softmax numerators
__device__ int   g_count[N_NODES];
__device__ int   g_offs[N_NODES];
__device__ int   g_cursor[N_NODES];
__device__ int   g_esrc[N_EDGES];
__device__ int   g_bsum[256];
__device__ int   g_boff[256];

__device__ __forceinline__ float leaky(float v) {
    return (v > 0.0f) ? v : NEG_SLOPE * v;
}

// ---------------- K0: prep — zero counts + build fp16 W'' = [W | W@Vsrc | W@Vdst | 0]
__global__ void prep_kernel(const float* __restrict__ W,
                            const float* __restrict__ att_src,
                            const float* __restrict__ att_dst) {
    int i = blockIdx.x * blockDim.x + threadIdx.x;
    if (i < N_NODES) g_count[i] = 0;
    if (i < 64 * W_COLS) {
        int k = i / W_COLS, c = i % W_COLS;
        float v;
        if (c < HC) {
            v = W[(size_t)k * HC + c];
        } else if (c < HC + 8) {
            int h = (c - HC) & 3;
            const float* av = (c < HC + 4) ? att_src : att_dst;
            float s = 0.0f;
            for (int t = 0; t < OUT_CH; t++)
                s += W[(size_t)k * HC + h * OUT_CH + t] * av[h * OUT_CH + t];
            v = s;
        } else {
            v = 0.0f;
        }
        g_Wh[i] = __float2half(v);
    }
}

// ---------------- K1: xt = x @ W'' on fp16 HMMA --------------------------------
// 256 threads (8 warps): warp = mw(0..3) x cw(0..1).
// mw: 16-node tile of the 64-node block; cw: col tiles [0,9) or [9,17).
// Tile 16 = logit columns. Dual accumulators hide HMMA latency.
// After A-frags are in registers, xa smem is reused as the epilogue stage.
__global__ void __launch_bounds__(256) gemm_kernel(const float* __restrict__ x) {
    __shared__ __align__(16) __half xa[GT_M * XA_LD];   // 9216 B; reused as stage
    __shared__ __align__(16) __half Ws[64 * W_LD];      // 35840 B

    const int tid  = threadIdx.x;
    const int warp = tid >> 5;
    const int lane = tid & 31;
    const int nblk = blockIdx.x * GT_M;

    // x tile [64 x 64] fp32 -> fp16 (zero-pad OOB)
    for (int i = tid; i < GT_M * IN_CH; i += 256) {
        int n = i >> 6, k = i & 63;
        int node = nblk + n;
        xa[n * XA_LD + k] = __float2half((node < N_NODES) ? x[(size_t)node * IN_CH + k] : 0.0f);
    }
    // W'' [64 x 272] vectorized into smem
    for (int i = tid; i < 64 * (W_COLS / 8); i += 256) {
        int k = i / (W_COLS / 8), c8 = i % (W_COLS / 8);
        *(uint4*)(Ws + k * W_LD + c8 * 8) = __ldg((const uint4*)(g_Wh + k * W_COLS) + c8);
    }
    __syncthreads();

    const int mw = warp >> 1;          // node tile 0..3
    const int cw = warp & 1;
    const int ct_begin = cw ? 9 : 0;
    const int ct_end   = cw ? 17 : 9;

    wmma::fragment<wmma::matrix_a, 16, 16, 16, __half, wmma::row_major> af[4];
#pragma unroll
    for (int kk = 0; kk < 4; kk++)
        wmma::load_matrix_sync(af[kk], xa + (mw * 16) * XA_LD + kk * 16, XA_LD);
    __syncthreads();    // all A-frags register-resident; xa becomes the stage

    float* st = (float*)xa + warp * (16 * 16);   // 1 KB per warp
    __half* xth = (__half*)g_xth;

    // epilogue for one finished tile
    auto emit = [&](int ct, wmma::fragment<wmma::accumulator, 16, 16, 16, float>& acc) {
        wmma::store_matrix_sync(st, acc, 16, wmma::mem_row_major);
        __syncwarp();
        if (ct < 16) {
            int row = lane & 15, ch = lane >> 4;
            int node = nblk + mw * 16 + row;
            if (node < N_NODES) {
                float4 u = *(const float4*)(st + row * 16 + ch * 8);
                float4 v = *(const float4*)(st + row * 16 + ch * 8 + 4);
                __half2 h0 = __floats2half2_rn(u.x, u.y);
                __half2 h1 = __floats2half2_rn(u.z, u.w);
                __half2 h2 = __floats2half2_rn(v.x, v.y);
                __half2 h3 = __floats2half2_rn(v.z, v.w);
                uint4 o = make_uint4(*(unsigned*)&h0, *(unsigned*)&h1,
                                     *(unsigned*)&h2, *(unsigned*)&h3);
                *(uint4*)(xth + (size_t)node * HC + ct * 16 + ch * 8) = o;
            }
        } else {
            if (lane < 16) {
                int node = nblk + mw * 16 + lane;
                if (node < N_NODES) {
                    *(float4*)(g_asrc + node * 4) = *(const float4*)(st + lane * 16);
                    *(float4*)(g_adst + node * 4) = *(const float4*)(st + lane * 16 + 4);
                }
            }
        }
        __syncwarp();
    };

    // main loop: tiles in pairs, dual accumulators interleaved
    for (int ct = ct_begin; ct < ct_end; ct += 2) {
        bool has2 = (ct + 1) < ct_end;
        wmma::fragment<wmma::accumulator, 16, 16, 16, float> acc0, acc1;
        wmma::fill_fragment(acc0, 0.0f);
        if (has2) wmma::fill_fragment(acc1, 0.0f);
#pragma unroll
        for (int kk = 0; kk < 4; kk++) {
            wmma::fragment<wmma::matrix_b, 16, 16, 16, __half, wmma::row_major> b0, b1;
            wmma::load_matrix_sync(b0, Ws + (kk * 16) * W_LD + ct * 16, W_LD);
            if (has2) wmma::load_matrix_sync(b1, Ws + (kk * 16) * W_LD + (ct + 1) * 16, W_LD);
            wmma::mma_sync(acc0, af[kk], b0, acc0);
            if (has2) wmma::mma_sync(acc1, af[kk], b1, acc1);
        }
        emit(ct, acc0);
        if (has2) emit(ct + 1, acc1);
    }
}

// ---------------- CSR build ----------------
__global__ void count_kernel(const int* __restrict__ ei) {
    int i = blockIdx.x * blockDim.x + threadIdx.x;
    if (i < N_EDGES / 4) {
        int4 d = __ldg((const int4*)(ei + N_EDGES) + i);
        atomicAdd(&g_count[d.x], 1);
        atomicAdd(&g_count[d.y], 1);
        atomicAdd(&g_count[d.z], 1);
        atomicAdd(&g_count[d.w], 1);
    }
}

__global__ void scanA_kernel() {
    __shared__ int wsum[8];
    int i = blockIdx.x * 256 + threadIdx.x;
    int c = (i < N_NODES) ? g_count[i] : 0;
    int v = c;
#pragma unroll
    for (int off = 16; off > 0; off >>= 1)
        v += __shfl_down_sync(0xFFFFFFFFu, v, off);
    if ((threadIdx.x & 31) == 0) wsum[threadIdx.x >> 5] = v;
    __syncthreads();
    if (threadIdx.x == 0) {
        int s = 0;
#pragma unroll
        for (int w = 0; w < 8; w++) s += wsum[w];
        g_bsum[blockIdx.x] = s;
    }
}

__global__ void scanB_kernel() {
    __shared__ int sm[256];
    int t = threadIdx.x;
    int v = (t < NBLK_NODES) ? g_bsum[t] : 0;
    sm[t] = v;
    __syncthreads();
    for (int off = 1; off < 256; off <<= 1) {
        int u = (t >= off) ? sm[t - off] : 0;
        __syncthreads();
        sm[t] += u;
        __syncthreads();
    }
    if (t < NBLK_NODES) g_boff[t] = sm[t] - v;
}

__global__ void scanC_kernel() {
    __shared__ int sm[256];
    int t = threadIdx.x;
    int i = blockIdx.x * 256 + t;
    int c = (i < N_NODES) ? g_count[i] : 0;
    sm[t] = c;
    __syncthreads();
    for (int off = 1; off < 256; off <<= 1) {
        int u = (t >= off) ? sm[t - off] : 0;
        __syncthreads();
        sm[t] += u;
        __syncthreads();
    }
    if (i < N_NODES) {
        int off = g_boff[blockIdx.x] + sm[t] - c;
        g_offs[i] = off;
        g_cursor[i] = off;
    }
}

// ---------------- scatter + edge-weight precompute ----------------
__global__ void scatter_kernel(const int* __restrict__ ei) {
    int i = blockIdx.x * blockDim.x + threadIdx.x;
    if (i >= N_EDGES) return;
    int src = __ldg(ei + i);
    int dst = __ldg(ei + N_EDGES + i);
    int pos = atomicAdd(&g_cursor[dst], 1);
    g_esrc[pos] = src;
    float4 as = *(const float4*)(g_asrc + src * 4);
    float4 ad = *(const float4*)(g_adst + dst * 4);
    float4 w;
    w.x = __expf(leaky(as.x + ad.x));
    w.y = __expf(leaky(as.y + ad.y));
    w.z = __expf(leaky(as.z + ad.z));
    w.w = __expf(leaky(as.w + ad.w));
    g_w[pos] = w;
}

// ---------------- agg: gather + head-mean + relu + fc (LDG.128 layout) --------
__global__ void agg_kernel(const float* __restrict__ bias,
                           const float* __restrict__ fc_w,
                           const float* __restrict__ fc_b,
                           float* __restrict__ out) {
    int i    = (blockIdx.x * blockDim.x + threadIdx.x) >> 5;
    int lane = threadIdx.x & 31;
    if (i >= N_NODES) return;

    const int h  = lane >> 3;
    const int cb = (lane & 7) * 8;
    const int start = g_offs[i];
    const int deg   = g_count[i];

    const float selfw = __expf(leaky(g_asrc[i * 4 + h] + g_adst[i * 4 + h]));
    const float* wflat = (const float*)g_w;

    float acc[8] = {0, 0, 0, 0, 0, 0, 0, 0};
    float s = 0.0f;

    int jn; float wn;
    if (deg > 0) { jn = __ldg(g_esrc + start); wn = __ldg(wflat + 4 * start + h); }
    else         { jn = i; wn = selfw; }

    for (int e = 0; e <= deg; e++) {
        int j = jn; float w = wn;
        int en = e + 1;
        if (en < deg)       { jn = __ldg(g_esrc + start + en); wn = __ldg(wflat + 4 * (start + en) + h); }
        else if (en == deg) { jn = i; wn = selfw; }

        s += w;
        uint4 v = __ldg((const uint4*)(g_xth + (size_t)j * (HC / 2)) + lane);
        float2 f0 = __half22float2(*(__half2*)&v.x);
        float2 f1 = __half22float2(*(__half2*)&v.y);
        float2 f2 = __half22float2(*(__half2*)&v.z);
        float2 f3 = __half22float2(*(__half2*)&v.w);
        acc[0] += w * f0.x; acc[1] += w * f0.y;
        acc[2] += w * f1.x; acc[3] += w * f1.y;
        acc[4] += w * f2.x; acc[5] += w * f2.y;
        acc[6] += w * f3.x; acc[7] += w * f3.y;
    }

    float inv = 0.25f / s;
#pragma unroll
    for (int c = 0; c < 8; c++) acc[c] *= inv;
#pragma unroll
    for (int c = 0; c < 8; c++) {
        acc[c] += __shfl_xor_sync(0xFFFFFFFFu, acc[c], 8);
        acc[c] += __shfl_xor_sync(0xFFFFFFFFu, acc[c], 16);
    }

    float4 b0 = __ldg((const float4*)(bias + cb));
    float4 b1 = __ldg((const float4*)(bias + cb + 4));
    float4 f0 = __ldg((const float4*)(fc_w + cb));
    float4 f1 = __ldg((const float4*)(fc_w + cb + 4));

    float p = fmaxf(acc[0] + b0.x, 0.0f) * f0.x
            + fmaxf(acc[1] + b0.y, 0.0f) * f0.y
            + fmaxf(acc[2] + b0.z, 0.0f) * f0.z
            + fmaxf(acc[3] + b0.w, 0.0f) * f0.w
            + fmaxf(acc[4] + b1.x, 0.0f) * f1.x
            + fmaxf(acc[5] + b1.y, 0.0f) * f1.y
            + fmaxf(acc[6] + b1.z, 0.0f) * f1.z
            + fmaxf(acc[7] + b1.w, 0.0f) * f1.w;

    p += __shfl_down_sync(0xFFFFFFFFu, p, 4, 8);
    p += __shfl_down_sync(0xFFFFFFFFu, p, 2, 8);
    p += __shfl_down_sync(0xFFFFFFFFu, p, 1, 8);

    if (lane == 0) out[i] = p + __ldg(fc_b);
}

// ---------------- launch ----------------
// gemm_kernel at launch index 3 (ncu capture slot) to verify the occupancy fix.
extern "C" void kernel_launch(void* const* d_in, const int* in_sizes, int n_in,
                              void* d_out, int out_size) {
    const float* x        = (const float*)d_in[0];
    const int*   ei       = (const int*)d_in[1];     // int32 [2, E]
    const float* W        = (const float*)d_in[2];
    const float* att_src  = (const float*)d_in[3];
    const float* att_dst  = (const float*)d_in[4];
    const float* bias     = (const float*)d_in[5];
    const float* fc_w     = (const float*)d_in[6];
    const float* fc_b     = (const float*)d_in[7];
    float*       out      = (float*)d_out;

    (void)in_sizes; (void)n_in; (void)out_size;

    prep_kernel<<<NBLK_NODES, 256>>>(W, att_src, att_dst);
    count_kernel<<<(N_EDGES / 4 + 255) / 256, 256>>>(ei);
    scanA_kernel<<<NBLK_NODES, 256>>>();
    gemm_kernel<<<NBLK_GEMM, 256>>>(x);                        // capture slot
    scanB_kernel<<<1, 256>>>();
    scanC_kernel<<<NBLK_NODES, 256>>>();
    scatter_kernel<<<(N_EDGES + 255) / 256, 256>>>(ei);
    agg_kernel<<<(N_NODES * 32 + 255) / 256, 256>>>(bias, fc_w, fc_b, out);
}